// round 5
// baseline (speedup 1.0000x reference)
#include <cuda_runtime.h>
#include <cstdint>

// x: (N=8, M=32, C=128, H=32, W=32) fp32.  D = H*W = 1024.
// 4096 independent classical Gram-Schmidt problems (one per (m,c)),
// each over NV=8 vectors of length 1024.
//
// Persistent pipelined version:
//  - grid = 592 = 148 SMs x 4 CTAs (one wave); each block processes ~7
//    problems (p = bid, bid+592, ...).
//  - problem t+1 is prefetched into a 32KB smem buffer with cp.async.cg
//    (LDGSTS.128) while problem t is computed from registers, so the DRAM
//    stream is decoupled from the barrier/reduction chain.
//  - Gram partials are pre-reduced 2 shuffle rounds before STS so the
//    partial buffer is only 9KB (static smem 41.6KB <= 48KB, 4 CTAs/SM).
#define NV 8
#define DLEN 1024
#define NPROB 4096
#define NSTRIDE_F4 (NPROB * DLEN / 4)   // 1048576 float4 between n-slices
#define NG 36                           // lower-triangular entries
#define GRID 592                        // 148 SMs * 4 CTAs

__device__ __forceinline__ float dot4(float4 a, float4 b) {
    return a.x * b.x + a.y * b.y + a.z * b.z + a.w * b.w;
}

__device__ __forceinline__ void cp_async16(uint32_t smem_dst, const void* gsrc) {
    asm volatile("cp.async.cg.shared.global [%0], [%1], 16;\n"
                 :: "r"(smem_dst), "l"(gsrc));
}

__global__ void __launch_bounds__(256, 4)
gram_schmidt_kernel(const float* __restrict__ x, float* __restrict__ out) {
    const int tid  = threadIdx.x;
    const int lane = tid & 31;
    const int warp = tid >> 5;

    __shared__ float4 buf[NV][256];   // 32KB: prefetch buffer for one problem
    __shared__ float part[NG][64];    // 9KB : pre-reduced Gram partials
    __shared__ float Gf[NG];          // reduced Gram (packed lower tri)
    __shared__ float Tm[NG];          // GS transform matrix (packed lower tri)

    const float4* __restrict__ xin4 = reinterpret_cast<const float4*>(x);
    float4* __restrict__ out4 = reinterpret_cast<float4*>(out);

    const uint32_t buf_base =
        (uint32_t)__cvta_generic_to_shared(&buf[0][0]) + (uint32_t)tid * 16u;

    // ---- prologue: prefetch first problem ----
    int p = blockIdx.x;
    {
        const float4* src = xin4 + (size_t)p * (DLEN / 4) + tid;
        #pragma unroll
        for (int n = 0; n < NV; n++) {
            cp_async16(buf_base + (uint32_t)n * (256u * 16u),
                       src + (size_t)n * NSTRIDE_F4);
        }
        asm volatile("cp.async.commit_group;\n");
    }

    for (; p < NPROB; p += GRID) {
        // ---- wait for this problem's data, make it CTA-visible ----
        asm volatile("cp.async.wait_group 0;\n" ::: "memory");
        __syncthreads();

        // ---- pull into registers ----
        float4 v[NV];
        #pragma unroll
        for (int n = 0; n < NV; n++) v[n] = buf[n][tid];
        __syncthreads();   // all reads of buf retired before overwrite

        // ---- kick off prefetch of next problem (overlaps everything below) ----
        const int pn = p + GRID;
        if (pn < NPROB) {
            const float4* src = xin4 + (size_t)pn * (DLEN / 4) + tid;
            #pragma unroll
            for (int n = 0; n < NV; n++) {
                cp_async16(buf_base + (uint32_t)n * (256u * 16u),
                           src + (size_t)n * NSTRIDE_F4);
            }
        }
        asm volatile("cp.async.commit_group;\n");

        // ---- Gram partials, pre-reduced 2 shuffle rounds, STS from lanes 0-7 ----
        #pragma unroll
        for (int i = 0; i < NV; i++) {
            #pragma unroll
            for (int j = 0; j <= i; j++) {
                float s = dot4(v[i], v[j]);
                s += __shfl_xor_sync(0xffffffffu, s, 16);
                s += __shfl_xor_sync(0xffffffffu, s, 8);
                if (lane < 8) part[i * (i + 1) / 2 + j][warp * 8 + lane] = s;
            }
        }
        __syncthreads();

        // ---- cooperative reduction: warp w handles entries w, w+8, ... ----
        for (int t = warp; t < NG; t += 8) {
            const float2* row = reinterpret_cast<const float2*>(part[t]);
            float2 a = row[lane];
            float s = a.x + a.y;
            s += __shfl_xor_sync(0xffffffffu, s, 16);
            s += __shfl_xor_sync(0xffffffffu, s, 8);
            s += __shfl_xor_sync(0xffffffffu, s, 4);
            s += __shfl_xor_sync(0xffffffffu, s, 2);
            s += __shfl_xor_sync(0xffffffffu, s, 1);
            if (lane == 0) Gf[t] = s;
        }
        __syncthreads();

        // ---- warp 0: triangular recursion Gram -> T (replicated lanes) ----
        if (warp == 0) {
            float G[NG];
            #pragma unroll
            for (int t = 0; t < NG; t++) G[t] = Gf[t];  // broadcast LDS

            float T[NG];
            {
                float inv = (G[0] > 0.0f) ? rsqrtf(G[0]) : 0.0f;
                T[0] = inv;
            }
            #pragma unroll
            for (int i = 1; i < NV; i++) {
                float c[NV];
                #pragma unroll
                for (int j = 0; j < i; j++) {
                    float s = 0.0f;
                    #pragma unroll
                    for (int k = 0; k <= j; k++)
                        s += T[j * (j + 1) / 2 + k] * G[i * (i + 1) / 2 + k];
                    c[j] = s;
                }
                float n2 = G[i * (i + 1) / 2 + i];
                #pragma unroll
                for (int j = 0; j < i; j++) n2 -= c[j] * c[j];
                float inv = (n2 > 0.0f) ? rsqrtf(n2) : 0.0f;

                #pragma unroll
                for (int k = 0; k < i; k++) {
                    float s = 0.0f;
                    #pragma unroll
                    for (int j = k; j < i; j++)
                        s -= c[j] * T[j * (j + 1) / 2 + k];
                    T[i * (i + 1) / 2 + k] = s * inv;
                }
                T[i * (i + 1) / 2 + i] = inv;
            }
            if (lane == 0) {
                #pragma unroll
                for (int t = 0; t < NG; t++) Tm[t] = T[t];
            }
        }
        __syncthreads();

        // ---- apply b_i = sum_{k<=i} T[i][k] v_k, store ----
        float4* __restrict__ dst = out4 + (size_t)p * (DLEN / 4) + tid;
        #pragma unroll
        for (int i = 0; i < NV; i++) {
            float4 acc = make_float4(0.0f, 0.0f, 0.0f, 0.0f);
            #pragma unroll
            for (int k = 0; k <= i; k++) {
                float t = Tm[i * (i + 1) / 2 + k];  // LDS broadcast
                acc.x += t * v[k].x;
                acc.y += t * v[k].y;
                acc.z += t * v[k].z;
                acc.w += t * v[k].w;
            }
            dst[(size_t)i * NSTRIDE_F4] = acc;
        }
    }
}

extern "C" void kernel_launch(void* const* d_in, const int* in_sizes, int n_in,
                              void* d_out, int out_size) {
    const float* x = (const float*)d_in[0];
    float* out = (float*)d_out;
    gram_schmidt_kernel<<<GRID, 256>>>(x, out);
}

// round 7
// speedup vs baseline: 1.0275x; 1.0275x over previous
#include <cuda_runtime.h>

// x: (N=8, M=32, C=128, H=32, W=32) fp32.  D = H*W = 1024.
// 4096 independent classical Gram-Schmidt problems (one per (m,c)),
// each over NV=8 vectors of length 1024.
//
// One block (256 threads) per problem, 1 float4 per thread per vector.
//  A) load 8 float4 (streaming), 36 packed-Gram dot4s, 1 shuffle pre-reduce,
//     STS to part[t][warp*16+lane] (18KB)
//  B) 8 warps cooperatively reduce the 36 entries (1 LDS.128 + 5 shuffles)
//  C) warp 0: triangular recursion Gram -> T (GS transform, inv norms on
//     the diagonal), broadcast via smem
//  D) apply b_i = sum_{k<=i} T[i][k] v_k, streaming store.
// __launch_bounds__(256,5) caps regs at 48 -> 5 CTAs/SM for latency hiding.
#define NV 8
#define DLEN 1024
#define NPROB 4096
#define NSTRIDE_F4 (NPROB * DLEN / 4)   // 1048576 float4 between n-slices
#define NG 36                           // lower-triangular entries

__device__ __forceinline__ float dot4(float4 a, float4 b) {
    return a.x * b.x + a.y * b.y + a.z * b.z + a.w * b.w;
}

__global__ void __launch_bounds__(256, 5)
gram_schmidt_kernel(const float* __restrict__ x, float* __restrict__ out) {
    const int p    = blockIdx.x;
    const int tid  = threadIdx.x;
    const int lane = tid & 31;
    const int warp = tid >> 5;

    const float4* __restrict__ xin =
        reinterpret_cast<const float4*>(x) + (size_t)p * (DLEN / 4) + tid;
    float4* __restrict__ xout =
        reinterpret_cast<float4*>(out) + (size_t)p * (DLEN / 4) + tid;

    __shared__ float part[NG][128];  // 18KB: half-reduced Gram partials
    __shared__ float Gf[NG];         // reduced Gram (packed lower tri)
    __shared__ float Tm[NG];         // GS transform matrix (packed lower tri)

    // ---- A: load all 8 vectors (batched LDG.128, evict-first) ----
    float4 v[NV];
    #pragma unroll
    for (int n = 0; n < NV; n++) v[n] = __ldcs(&xin[(size_t)n * NSTRIDE_F4]);

    // partial Gram, pre-reduced one shuffle round (lanes 0-15 store)
    #pragma unroll
    for (int i = 0; i < NV; i++) {
        #pragma unroll
        for (int j = 0; j <= i; j++) {
            float s = dot4(v[i], v[j]);
            s += __shfl_xor_sync(0xffffffffu, s, 16);
            if (lane < 16) part[i * (i + 1) / 2 + j][warp * 16 + lane] = s;
        }
    }
    __syncthreads();

    // ---- B: cooperative reduction, warp w handles entries w, w+8, ... ----
    for (int t = warp; t < NG; t += 8) {
        const float4* row = reinterpret_cast<const float4*>(part[t]);
        float4 a = row[lane];                 // 32 lanes x float4 = 128 floats
        float s = (a.x + a.y) + (a.z + a.w);
        s += __shfl_xor_sync(0xffffffffu, s, 16);
        s += __shfl_xor_sync(0xffffffffu, s, 8);
        s += __shfl_xor_sync(0xffffffffu, s, 4);
        s += __shfl_xor_sync(0xffffffffu, s, 2);
        s += __shfl_xor_sync(0xffffffffu, s, 1);
        if (lane == 0) Gf[t] = s;
    }
    __syncthreads();

    // ---- C: warp 0 computes the triangular recursion (replicated lanes) ----
    if (warp == 0) {
        float G[NG];
        #pragma unroll
        for (int t = 0; t < NG; t++) G[t] = Gf[t];  // broadcast LDS

        float T[NG];
        {
            float inv = (G[0] > 0.0f) ? rsqrtf(G[0]) : 0.0f;
            T[0] = inv;
        }
        #pragma unroll
        for (int i = 1; i < NV; i++) {
            float c[NV];
            #pragma unroll
            for (int j = 0; j < i; j++) {
                float s = 0.0f;
                #pragma unroll
                for (int k = 0; k <= j; k++)
                    s += T[j * (j + 1) / 2 + k] * G[i * (i + 1) / 2 + k];
                c[j] = s;
            }
            float n2 = G[i * (i + 1) / 2 + i];
            #pragma unroll
            for (int j = 0; j < i; j++) n2 -= c[j] * c[j];
            float inv = (n2 > 0.0f) ? rsqrtf(n2) : 0.0f;

            #pragma unroll
            for (int k = 0; k < i; k++) {
                float s = 0.0f;
                #pragma unroll
                for (int j = k; j < i; j++)
                    s -= c[j] * T[j * (j + 1) / 2 + k];
                T[i * (i + 1) / 2 + k] = s * inv;
            }
            T[i * (i + 1) / 2 + i] = inv;
        }
        if (lane == 0) {
            #pragma unroll
            for (int t = 0; t < NG; t++) Tm[t] = T[t];
        }
    }
    __syncthreads();

    // ---- D: apply b_i = sum_{k<=i} T[i][k] v_k, streaming store ----
    #pragma unroll
    for (int i = 0; i < NV; i++) {
        float4 acc = make_float4(0.0f, 0.0f, 0.0f, 0.0f);
        #pragma unroll
        for (int k = 0; k <= i; k++) {
            float t = Tm[i * (i + 1) / 2 + k];  // LDS broadcast
            acc.x += t * v[k].x;
            acc.y += t * v[k].y;
            acc.z += t * v[k].z;
            acc.w += t * v[k].w;
        }
        __stcs(&xout[(size_t)i * NSTRIDE_F4], acc);
    }
}

extern "C" void kernel_launch(void* const* d_in, const int* in_sizes, int n_in,
                              void* d_out, int out_size) {
    const float* x = (const float*)d_in[0];
    float* out = (float*)d_out;
    gram_schmidt_kernel<<<NPROB, 256>>>(x, out);
}